// round 6
// baseline (speedup 1.0000x reference)
#include <cuda_runtime.h>
#include <cstdint>

#define HID 128
#define H2  256
#define MAXN 50048   // scratch capacity (N = 50000 in this problem; must be < 65536 for packing)
#define MAXE 800000

// ---------------- device scratch (no allocations allowed) ----------------
__device__ __align__(128) float g_h[MAXN * HID];     // encoded+masked node features
__device__ __align__(128) float g_aggr[MAXN * HID];  // aggregation buffer
__device__ __align__(128) float g_t[MAXN * H2];      // MLP hidden
__device__ int g_deg[MAXN];          // per-dst degree
__device__ int g_off[MAXN + 1];      // CSR offsets
__device__ int g_cur[MAXN];          // scatter cursors
__device__ int g_eid[MAXE];          // packed: src | (combo<<16)

// =========================================================================
// GEMM1: h = prelu(x) @ Wenc^T ; aggr = h + (emb1[4]+emb2[0])  (self-loop)
// =========================================================================
__global__ __launch_bounds__(256, 2) void gemm1_kernel(
    const float* __restrict__ x, const float* __restrict__ Wenc,
    const float* __restrict__ emb1, const float* __restrict__ emb2,
    const float* __restrict__ prelu_a, int N)
{
    extern __shared__ float sm[];
    float* Wt = sm;               // [128][132]
    float* As = sm + 128 * 132;   // [64][132]

    const int tid = threadIdx.x;
    for (int idx = tid; idx < 128 * 128; idx += 256) {
        int j = idx >> 7, k = idx & 127;
        Wt[k * 132 + j] = Wenc[idx];
    }
    const float pa = *prelu_a;
    const int row0 = blockIdx.x * 64;

    for (int idx = tid; idx < 64 * 32; idx += 256) {
        int r = idx >> 5, kk = (idx & 31) * 4;
        int gr = row0 + r;
        float4 v = make_float4(0.f, 0.f, 0.f, 0.f);
        if (gr < N) v = *(const float4*)(x + (size_t)gr * HID + kk);
        v.x = v.x > 0.f ? v.x : pa * v.x;
        v.y = v.y > 0.f ? v.y : pa * v.y;
        v.z = v.z > 0.f ? v.z : pa * v.z;
        v.w = v.w > 0.f ? v.w : pa * v.w;
        *(float4*)(As + r * 132 + kk) = v;
    }
    __syncthreads();

    const int tc = tid & 31;
    const int tr = tid >> 5;

    float acc[8][4];
#pragma unroll
    for (int r = 0; r < 8; r++)
#pragma unroll
        for (int c = 0; c < 4; c++) acc[r][c] = 0.f;

#pragma unroll 2
    for (int k = 0; k < 128; k += 4) {
        float4 w0 = *(const float4*)(Wt + (k + 0) * 132 + tc * 4);
        float4 w1 = *(const float4*)(Wt + (k + 1) * 132 + tc * 4);
        float4 w2 = *(const float4*)(Wt + (k + 2) * 132 + tc * 4);
        float4 w3 = *(const float4*)(Wt + (k + 3) * 132 + tc * 4);
#pragma unroll
        for (int rr = 0; rr < 8; rr++) {
            float4 a = *(const float4*)(As + (tr + rr * 8) * 132 + k);
            acc[rr][0] += a.x * w0.x + a.y * w1.x + a.z * w2.x + a.w * w3.x;
            acc[rr][1] += a.x * w0.y + a.y * w1.y + a.z * w2.y + a.w * w3.y;
            acc[rr][2] += a.x * w0.z + a.y * w1.z + a.z * w2.z + a.w * w3.z;
            acc[rr][3] += a.x * w0.w + a.y * w1.w + a.z * w2.w + a.w * w3.w;
        }
    }

    float sl[4];
#pragma unroll
    for (int c = 0; c < 4; c++)
        sl[c] = emb1[4 * HID + tc * 4 + c] + emb2[tc * 4 + c];

#pragma unroll
    for (int rr = 0; rr < 8; rr++) {
        int gr = row0 + tr + rr * 8;
        if (gr < N) {
            float4 hv = make_float4(acc[rr][0], acc[rr][1], acc[rr][2], acc[rr][3]);
            *(float4*)(g_h + (size_t)gr * HID + tc * 4) = hv;
            float4 av = make_float4(hv.x + sl[0], hv.y + sl[1], hv.z + sl[2], hv.w + sl[3]);
            *(float4*)(g_aggr + (size_t)gr * HID + tc * 4) = av;
        }
    }
}

// =========================================================================
// Mask: h[m]=0 ; aggr[m]=sl_emb  (idempotent under duplicate indices)
// =========================================================================
__global__ void mask_kernel(const int* __restrict__ mask,
                            const float* __restrict__ emb1,
                            const float* __restrict__ emb2)
{
    int node = mask[blockIdx.x];
    int t = threadIdx.x;  // 128 threads
    g_h[(size_t)node * HID + t] = 0.f;
    g_aggr[(size_t)node * HID + t] = emb1[4 * HID + t] + emb2[t];
}

// =========================================================================
// CSR build: deg histogram -> scan -> packed scatter
// =========================================================================
__global__ void zero_deg_kernel(int N)
{
    int i = blockIdx.x * blockDim.x + threadIdx.x;
    if (i < N) g_deg[i] = 0;
}

__global__ void hist_kernel(const int* __restrict__ ei, int E)
{
    int e = blockIdx.x * blockDim.x + threadIdx.x;
    if (e < E) atomicAdd(&g_deg[ei[E + e]], 1);
}

// single-block exclusive scan over N (N <= 1024*chunk)
__global__ __launch_bounds__(1024) void scan_kernel(int N, int E)
{
    __shared__ int part[1024];
    const int tid = threadIdx.x;
    const int chunk = (N + 1023) / 1024;
    const int lo = tid * chunk;
    const int hi = min(lo + chunk, N);

    int s = 0;
    for (int i = lo; i < hi; i++) s += g_deg[i];
    part[tid] = s;
    __syncthreads();

    // Hillis-Steele inclusive scan
    for (int d = 1; d < 1024; d <<= 1) {
        int v = (tid >= d) ? part[tid - d] : 0;
        __syncthreads();
        part[tid] += v;
        __syncthreads();
    }
    int base = part[tid] - s;  // exclusive prefix for this thread's chunk

    for (int i = lo; i < hi; i++) {
        g_off[i] = base;
        g_cur[i] = base;
        base += g_deg[i];
    }
    if (tid == 1023) g_off[N] = E;
}

__global__ void scatter_kernel(const int* __restrict__ ei,
                               const int* __restrict__ attr, int E)
{
    int e = blockIdx.x * blockDim.x + threadIdx.x;
    if (e < E) {
        int src = ei[e];
        int dst = ei[E + e];
        int2 aa = *(const int2*)(attr + 2 * (size_t)e);
        int pos = atomicAdd(&g_cur[dst], 1);
        g_eid[pos] = src | ((aa.x * 3 + aa.y) << 16);
    }
}

// =========================================================================
// Aggregate: one warp per dst node, no atomics.
// aggr[n] = aggr_init[n] + sum_{e in CSR(n)} (h[src_e] + combo[e])
// =========================================================================
__global__ __launch_bounds__(256) void aggregate_kernel(
    const float* __restrict__ emb1, const float* __restrict__ emb2, int N)
{
    __shared__ float combos[18][HID];
    const int tid = threadIdx.x;
    for (int idx = tid; idx < 18 * HID; idx += 256) {
        int c = idx >> 7, k = idx & 127;
        combos[c][k] = emb1[(c / 3) * HID + k] + emb2[(c % 3) * HID + k];
    }
    __syncthreads();

    const int lane = tid & 31;
    const int node = blockIdx.x * 8 + (tid >> 5);
    if (node >= N) return;

    const int base0 = g_off[node];
    const int cnt = g_off[node + 1] - base0;

    float4 acc = make_float4(0.f, 0.f, 0.f, 0.f);

    for (int b = 0; b < cnt; b += 32) {
        int p = 0;
        if (b + lane < cnt) p = g_eid[base0 + b + lane];
        int m = cnt - b; if (m > 32) m = 32;
        for (int i = 0; i < m; i++) {
            int pp = __shfl_sync(0xffffffffu, p, i);
            int s = pp & 0xFFFF;
            int cb = pp >> 16;
            float4 hv = *(const float4*)(g_h + (size_t)s * HID + lane * 4);
            float4 ev = *(const float4*)(&combos[cb][lane * 4]);
            acc.x += hv.x + ev.x;
            acc.y += hv.y + ev.y;
            acc.z += hv.z + ev.z;
            acc.w += hv.w + ev.w;
        }
    }

    float* ap = g_aggr + (size_t)node * HID + lane * 4;
    float4 init = *(const float4*)ap;
    init.x += acc.x; init.y += acc.y; init.z += acc.z; init.w += acc.w;
    *(float4*)ap = init;
}

// =========================================================================
// GEMM2: t = relu(aggr @ W1^T + b1)   [N,128] -> [N,256], col-split grid.y=2
// =========================================================================
__global__ __launch_bounds__(256, 2) void gemm2_kernel(
    const float* __restrict__ W1, const float* __restrict__ b1, int N)
{
    extern __shared__ float sm[];
    float* Wt = sm;               // [128][132]  Wt[k][j] = W1[col0+j][k]
    float* As = sm + 128 * 132;   // [64][132]

    const int tid = threadIdx.x;
    const int col0 = blockIdx.y * 128;
    for (int idx = tid; idx < 128 * 128; idx += 256) {
        int j = idx >> 7, k = idx & 127;
        Wt[k * 132 + j] = W1[(size_t)(col0 + j) * HID + k];
    }
    const int row0 = blockIdx.x * 64;
    for (int idx = tid; idx < 64 * 32; idx += 256) {
        int r = idx >> 5, kk = (idx & 31) * 4;
        int gr = row0 + r;
        float4 v = make_float4(0.f, 0.f, 0.f, 0.f);
        if (gr < N) v = *(const float4*)(g_aggr + (size_t)gr * HID + kk);
        *(float4*)(As + r * 132 + kk) = v;
    }
    __syncthreads();

    const int tc = tid & 31;
    const int tr = tid >> 5;

    float acc[8][4];
#pragma unroll
    for (int r = 0; r < 8; r++)
#pragma unroll
        for (int c = 0; c < 4; c++) acc[r][c] = 0.f;

#pragma unroll 2
    for (int k = 0; k < 128; k += 4) {
        float4 w0 = *(const float4*)(Wt + (k + 0) * 132 + tc * 4);
        float4 w1 = *(const float4*)(Wt + (k + 1) * 132 + tc * 4);
        float4 w2 = *(const float4*)(Wt + (k + 2) * 132 + tc * 4);
        float4 w3 = *(const float4*)(Wt + (k + 3) * 132 + tc * 4);
#pragma unroll
        for (int rr = 0; rr < 8; rr++) {
            float4 a = *(const float4*)(As + (tr + rr * 8) * 132 + k);
            acc[rr][0] += a.x * w0.x + a.y * w1.x + a.z * w2.x + a.w * w3.x;
            acc[rr][1] += a.x * w0.y + a.y * w1.y + a.z * w2.y + a.w * w3.y;
            acc[rr][2] += a.x * w0.z + a.y * w1.z + a.z * w2.z + a.w * w3.z;
            acc[rr][3] += a.x * w0.w + a.y * w1.w + a.z * w2.w + a.w * w3.w;
        }
    }

    float bb[4];
#pragma unroll
    for (int c = 0; c < 4; c++) bb[c] = b1[col0 + tc * 4 + c];

#pragma unroll
    for (int rr = 0; rr < 8; rr++) {
        int gr = row0 + tr + rr * 8;
        if (gr < N) {
            float4 o;
            o.x = fmaxf(acc[rr][0] + bb[0], 0.f);
            o.y = fmaxf(acc[rr][1] + bb[1], 0.f);
            o.z = fmaxf(acc[rr][2] + bb[2], 0.f);
            o.w = fmaxf(acc[rr][3] + bb[3], 0.f);
            *(float4*)(g_t + (size_t)gr * H2 + col0 + tc * 4) = o;
        }
    }
}

// =========================================================================
// GEMM3: out = t @ W2^T + b2   [N,256] -> [N,128], two-phase K
// =========================================================================
__global__ __launch_bounds__(256, 2) void gemm3_kernel(
    const float* __restrict__ W2, const float* __restrict__ b2,
    float* __restrict__ out, int N)
{
    extern __shared__ float sm[];
    float* Wt = sm;               // [128][132]
    float* As = sm + 128 * 132;   // [32][260]

    const int tid = threadIdx.x;
    const int row0 = blockIdx.x * 32;
    for (int idx = tid; idx < 32 * 64; idx += 256) {
        int r = idx >> 6, kk = (idx & 63) * 4;
        int gr = row0 + r;
        float4 v = make_float4(0.f, 0.f, 0.f, 0.f);
        if (gr < N) v = *(const float4*)(g_t + (size_t)gr * H2 + kk);
        *(float4*)(As + r * 260 + kk) = v;
    }

    const int tc = tid & 31;
    const int tr = tid >> 5;

    float acc[4][4];
#pragma unroll
    for (int r = 0; r < 4; r++)
#pragma unroll
        for (int c = 0; c < 4; c++) acc[r][c] = 0.f;

#pragma unroll
    for (int ph = 0; ph < 2; ph++) {
        __syncthreads();
        for (int idx = tid; idx < 128 * 128; idx += 256) {
            int j = idx >> 7, k = idx & 127;
            Wt[k * 132 + j] = W2[(size_t)j * H2 + ph * 128 + k];
        }
        __syncthreads();

        const float* Asp = As + ph * 128;
#pragma unroll 2
        for (int k = 0; k < 128; k += 4) {
            float4 w0 = *(const float4*)(Wt + (k + 0) * 132 + tc * 4);
            float4 w1 = *(const float4*)(Wt + (k + 1) * 132 + tc * 4);
            float4 w2 = *(const float4*)(Wt + (k + 2) * 132 + tc * 4);
            float4 w3 = *(const float4*)(Wt + (k + 3) * 132 + tc * 4);
#pragma unroll
            for (int rr = 0; rr < 4; rr++) {
                float4 a = *(const float4*)(Asp + (tr + rr * 8) * 260 + k);
                acc[rr][0] += a.x * w0.x + a.y * w1.x + a.z * w2.x + a.w * w3.x;
                acc[rr][1] += a.x * w0.y + a.y * w1.y + a.z * w2.y + a.w * w3.y;
                acc[rr][2] += a.x * w0.z + a.y * w1.z + a.z * w2.z + a.w * w3.z;
                acc[rr][3] += a.x * w0.w + a.y * w1.w + a.z * w2.w + a.w * w3.w;
            }
        }
    }

    float bb[4];
#pragma unroll
    for (int c = 0; c < 4; c++) bb[c] = b2[tc * 4 + c];

#pragma unroll
    for (int rr = 0; rr < 4; rr++) {
        int gr = row0 + tr + rr * 8;
        if (gr < N) {
            float4 o;
            o.x = acc[rr][0] + bb[0];
            o.y = acc[rr][1] + bb[1];
            o.z = acc[rr][2] + bb[2];
            o.w = acc[rr][3] + bb[3];
            *(float4*)(out + (size_t)gr * HID + tc * 4) = o;
        }
    }
}

// =========================================================================
// launch
// =========================================================================
extern "C" void kernel_launch(void* const* d_in, const int* in_sizes, int n_in,
                              void* d_out, int out_size)
{
    const float* x       = (const float*)d_in[0];
    const int*   ei      = (const int*)  d_in[1];
    const int*   attr    = (const int*)  d_in[2];
    const int*   mask    = (const int*)  d_in[3];
    const float* prelu_a = (const float*)d_in[4];
    const float* Wenc    = (const float*)d_in[5];
    const float* W1      = (const float*)d_in[6];
    const float* b1      = (const float*)d_in[7];
    const float* W2      = (const float*)d_in[8];
    const float* b2      = (const float*)d_in[9];
    const float* emb1    = (const float*)d_in[10];
    const float* emb2    = (const float*)d_in[11];
    float* out = (float*)d_out;

    int N = in_sizes[0] / HID;
    int E = in_sizes[1] / 2;
    int M = in_sizes[3];

    const int SM1 = (128 * 132 + 64 * 132) * 4;   // 101 376 B
    const int SM2 = (128 * 132 + 64 * 132) * 4;   // 101 376 B
    const int SM3 = (128 * 132 + 32 * 260) * 4;   // 100 864 B
    cudaFuncSetAttribute(gemm1_kernel, cudaFuncAttributeMaxDynamicSharedMemorySize, SM1);
    cudaFuncSetAttribute(gemm2_kernel, cudaFuncAttributeMaxDynamicSharedMemorySize, SM2);
    cudaFuncSetAttribute(gemm3_kernel, cudaFuncAttributeMaxDynamicSharedMemorySize, SM3);

    // CSR build (independent of node features)
    zero_deg_kernel<<<(N + 255) / 256, 256>>>(N);
    hist_kernel<<<(E + 255) / 256, 256>>>(ei, E);
    scan_kernel<<<1, 1024>>>(N, E);
    scatter_kernel<<<(E + 255) / 256, 256>>>(ei, attr, E);

    int rowBlocks64 = (N + 63) / 64;
    gemm1_kernel<<<rowBlocks64, 256, SM1>>>(x, Wenc, emb1, emb2, prelu_a, N);
    if (M > 0) mask_kernel<<<M, HID>>>(mask, emb1, emb2);

    aggregate_kernel<<<(N + 7) / 8, 256>>>(emb1, emb2, N);

    dim3 g2(rowBlocks64, 2);
    gemm2_kernel<<<g2, 256, SM2>>>(W1, b1, N);

    int rowBlocks32 = (N + 31) / 32;
    gemm3_kernel<<<rowBlocks32, 256, SM3>>>(W2, b2, out, N);
}

// round 7
// speedup vs baseline: 1.1703x; 1.1703x over previous
#include <cuda_runtime.h>
#include <cstdint>

#define HID 128
#define H2  256
#define MAXN 50048   // scratch capacity (N = 50000 in this problem)

// ---------------- device scratch (no allocations allowed) ----------------
__device__ __align__(128) float g_h[MAXN * HID];     // encoded+masked node features
__device__ __align__(128) float g_aggr[MAXN * HID];  // aggregation buffer
__device__ __align__(128) float g_t[MAXN * H2];      // MLP hidden

// =========================================================================
// GEMM1: h = prelu(x) @ Wenc^T ; aggr = h + (emb1[4]+emb2[0])  (self-loop)
// =========================================================================
__global__ __launch_bounds__(256, 2) void gemm1_kernel(
    const float* __restrict__ x, const float* __restrict__ Wenc,
    const float* __restrict__ emb1, const float* __restrict__ emb2,
    const float* __restrict__ prelu_a, int N)
{
    extern __shared__ float sm[];
    float* Wt = sm;               // [128][132]
    float* As = sm + 128 * 132;   // [64][132]

    const int tid = threadIdx.x;
    for (int idx = tid; idx < 128 * 128; idx += 256) {
        int j = idx >> 7, k = idx & 127;
        Wt[k * 132 + j] = Wenc[idx];
    }
    const float pa = *prelu_a;
    const int row0 = blockIdx.x * 64;

    for (int idx = tid; idx < 64 * 32; idx += 256) {
        int r = idx >> 5, kk = (idx & 31) * 4;
        int gr = row0 + r;
        float4 v = make_float4(0.f, 0.f, 0.f, 0.f);
        if (gr < N) v = *(const float4*)(x + (size_t)gr * HID + kk);
        v.x = v.x > 0.f ? v.x : pa * v.x;
        v.y = v.y > 0.f ? v.y : pa * v.y;
        v.z = v.z > 0.f ? v.z : pa * v.z;
        v.w = v.w > 0.f ? v.w : pa * v.w;
        *(float4*)(As + r * 132 + kk) = v;
    }
    __syncthreads();

    const int tc = tid & 31;
    const int tr = tid >> 5;

    float acc[8][4];
#pragma unroll
    for (int r = 0; r < 8; r++)
#pragma unroll
        for (int c = 0; c < 4; c++) acc[r][c] = 0.f;

#pragma unroll 2
    for (int k = 0; k < 128; k += 4) {
        float4 w0 = *(const float4*)(Wt + (k + 0) * 132 + tc * 4);
        float4 w1 = *(const float4*)(Wt + (k + 1) * 132 + tc * 4);
        float4 w2 = *(const float4*)(Wt + (k + 2) * 132 + tc * 4);
        float4 w3 = *(const float4*)(Wt + (k + 3) * 132 + tc * 4);
#pragma unroll
        for (int rr = 0; rr < 8; rr++) {
            float4 a = *(const float4*)(As + (tr + rr * 8) * 132 + k);
            acc[rr][0] += a.x * w0.x + a.y * w1.x + a.z * w2.x + a.w * w3.x;
            acc[rr][1] += a.x * w0.y + a.y * w1.y + a.z * w2.y + a.w * w3.y;
            acc[rr][2] += a.x * w0.z + a.y * w1.z + a.z * w2.z + a.w * w3.z;
            acc[rr][3] += a.x * w0.w + a.y * w1.w + a.z * w2.w + a.w * w3.w;
        }
    }

    float sl[4];
#pragma unroll
    for (int c = 0; c < 4; c++)
        sl[c] = emb1[4 * HID + tc * 4 + c] + emb2[tc * 4 + c];

#pragma unroll
    for (int rr = 0; rr < 8; rr++) {
        int gr = row0 + tr + rr * 8;
        if (gr < N) {
            float4 hv = make_float4(acc[rr][0], acc[rr][1], acc[rr][2], acc[rr][3]);
            *(float4*)(g_h + (size_t)gr * HID + tc * 4) = hv;
            float4 av = make_float4(hv.x + sl[0], hv.y + sl[1], hv.z + sl[2], hv.w + sl[3]);
            *(float4*)(g_aggr + (size_t)gr * HID + tc * 4) = av;
        }
    }
}

// =========================================================================
// Mask (split in two so edge_kernel is the 4th launch -> gets ncu capture)
// =========================================================================
__global__ void mask_h_kernel(const int* __restrict__ mask)
{
    int node = mask[blockIdx.x];
    g_h[(size_t)node * HID + threadIdx.x] = 0.f;
}

__global__ void mask_aggr_kernel(const int* __restrict__ mask,
                                 const float* __restrict__ emb1,
                                 const float* __restrict__ emb2)
{
    int node = mask[blockIdx.x];
    int t = threadIdx.x;
    g_aggr[(size_t)node * HID + t] = emb1[4 * HID + t] + emb2[t];
}

// =========================================================================
// Edge scatter v2: aggr[dst] += h[src] + (emb1[a0]+emb2[a1])
// Warp stages its 32 edge descriptors in smem (no shfl chains), then an
// unrolled inner loop keeps 4 independent 512B gathers in flight.
// =========================================================================
__global__ __launch_bounds__(256) void edge_kernel(
    const int* __restrict__ ei, const int* __restrict__ attr,
    const float* __restrict__ emb1, const float* __restrict__ emb2, int E)
{
    __shared__ float combos[18][HID];   // emb1[a]+emb2[b] for a<6, b<3
    __shared__ int s_src[8][32];
    __shared__ int s_meta[8][32];

    const int tid = threadIdx.x;
    for (int idx = tid; idx < 18 * HID; idx += 256) {
        int c = idx >> 7, k = idx & 127;
        combos[c][k] = emb1[(c / 3) * HID + k] + emb2[(c % 3) * HID + k];
    }
    __syncthreads();

    const int lane = tid & 31;
    const int wi = tid >> 5;
    const int warp = blockIdx.x * 8 + wi;

    const int base = warp * 32;
    if (base >= E) return;
    int cnt = E - base; if (cnt > 32) cnt = 32;

    {
        int e = base + lane;
        if (e < E) {
            s_src[wi][lane] = ei[e];
            int2 aa = *(const int2*)(attr + 2 * (size_t)e);
            s_meta[wi][lane] = ei[E + e] | ((aa.x * 3 + aa.y) << 20);
        }
    }
    __syncwarp();

    const int fo = lane * 4;   // this lane's float4 slice of the 128-dim row

    if (cnt == 32) {
#pragma unroll 4
        for (int i = 0; i < 32; i++) {
            int s = s_src[wi][i];
            int m = s_meta[wi][i];
            int d = m & 0xFFFFF;
            int cb = m >> 20;
            float4 hv = *(const float4*)(g_h + (size_t)s * HID + fo);
            float4 ev = *(const float4*)(&combos[cb][fo]);
            float vx = hv.x + ev.x, vy = hv.y + ev.y, vz = hv.z + ev.z, vw = hv.w + ev.w;
            float* p = g_aggr + (size_t)d * HID + fo;
            asm volatile("red.global.add.v4.f32 [%0], {%1,%2,%3,%4};"
                         :: "l"(p), "f"(vx), "f"(vy), "f"(vz), "f"(vw)
                         : "memory");
        }
    } else {
        for (int i = 0; i < cnt; i++) {
            int s = s_src[wi][i];
            int m = s_meta[wi][i];
            int d = m & 0xFFFFF;
            int cb = m >> 20;
            float4 hv = *(const float4*)(g_h + (size_t)s * HID + fo);
            float4 ev = *(const float4*)(&combos[cb][fo]);
            float vx = hv.x + ev.x, vy = hv.y + ev.y, vz = hv.z + ev.z, vw = hv.w + ev.w;
            float* p = g_aggr + (size_t)d * HID + fo;
            asm volatile("red.global.add.v4.f32 [%0], {%1,%2,%3,%4};"
                         :: "l"(p), "f"(vx), "f"(vy), "f"(vz), "f"(vw)
                         : "memory");
        }
    }
}

// =========================================================================
// GEMM2: t = relu(aggr @ W1^T + b1)   [N,128] -> [N,256], col-split grid.y=2
// =========================================================================
__global__ __launch_bounds__(256, 2) void gemm2_kernel(
    const float* __restrict__ W1, const float* __restrict__ b1, int N)
{
    extern __shared__ float sm[];
    float* Wt = sm;               // [128][132]  Wt[k][j] = W1[col0+j][k]
    float* As = sm + 128 * 132;   // [64][132]

    const int tid = threadIdx.x;
    const int col0 = blockIdx.y * 128;
    for (int idx = tid; idx < 128 * 128; idx += 256) {
        int j = idx >> 7, k = idx & 127;
        Wt[k * 132 + j] = W1[(size_t)(col0 + j) * HID + k];
    }
    const int row0 = blockIdx.x * 64;
    for (int idx = tid; idx < 64 * 32; idx += 256) {
        int r = idx >> 5, kk = (idx & 31) * 4;
        int gr = row0 + r;
        float4 v = make_float4(0.f, 0.f, 0.f, 0.f);
        if (gr < N) v = *(const float4*)(g_aggr + (size_t)gr * HID + kk);
        *(float4*)(As + r * 132 + kk) = v;
    }
    __syncthreads();

    const int tc = tid & 31;
    const int tr = tid >> 5;

    float acc[8][4];
#pragma unroll
    for (int r = 0; r < 8; r++)
#pragma unroll
        for (int c = 0; c < 4; c++) acc[r][c] = 0.f;

#pragma unroll 2
    for (int k = 0; k < 128; k += 4) {
        float4 w0 = *(const float4*)(Wt + (k + 0) * 132 + tc * 4);
        float4 w1 = *(const float4*)(Wt + (k + 1) * 132 + tc * 4);
        float4 w2 = *(const float4*)(Wt + (k + 2) * 132 + tc * 4);
        float4 w3 = *(const float4*)(Wt + (k + 3) * 132 + tc * 4);
#pragma unroll
        for (int rr = 0; rr < 8; rr++) {
            float4 a = *(const float4*)(As + (tr + rr * 8) * 132 + k);
            acc[rr][0] += a.x * w0.x + a.y * w1.x + a.z * w2.x + a.w * w3.x;
            acc[rr][1] += a.x * w0.y + a.y * w1.y + a.z * w2.y + a.w * w3.y;
            acc[rr][2] += a.x * w0.z + a.y * w1.z + a.z * w2.z + a.w * w3.z;
            acc[rr][3] += a.x * w0.w + a.y * w1.w + a.z * w2.w + a.w * w3.w;
        }
    }

    float bb[4];
#pragma unroll
    for (int c = 0; c < 4; c++) bb[c] = b1[col0 + tc * 4 + c];

#pragma unroll
    for (int rr = 0; rr < 8; rr++) {
        int gr = row0 + tr + rr * 8;
        if (gr < N) {
            float4 o;
            o.x = fmaxf(acc[rr][0] + bb[0], 0.f);
            o.y = fmaxf(acc[rr][1] + bb[1], 0.f);
            o.z = fmaxf(acc[rr][2] + bb[2], 0.f);
            o.w = fmaxf(acc[rr][3] + bb[3], 0.f);
            *(float4*)(g_t + (size_t)gr * H2 + col0 + tc * 4) = o;
        }
    }
}

// =========================================================================
// GEMM3: out = t @ W2^T + b2   [N,256] -> [N,128], two-phase K
// =========================================================================
__global__ __launch_bounds__(256, 2) void gemm3_kernel(
    const float* __restrict__ W2, const float* __restrict__ b2,
    float* __restrict__ out, int N)
{
    extern __shared__ float sm[];
    float* Wt = sm;               // [128][132]
    float* As = sm + 128 * 132;   // [32][260]

    const int tid = threadIdx.x;
    const int row0 = blockIdx.x * 32;
    for (int idx = tid; idx < 32 * 64; idx += 256) {
        int r = idx >> 6, kk = (idx & 63) * 4;
        int gr = row0 + r;
        float4 v = make_float4(0.f, 0.f, 0.f, 0.f);
        if (gr < N) v = *(const float4*)(g_t + (size_t)gr * H2 + kk);
        *(float4*)(As + r * 260 + kk) = v;
    }

    const int tc = tid & 31;
    const int tr = tid >> 5;

    float acc[4][4];
#pragma unroll
    for (int r = 0; r < 4; r++)
#pragma unroll
        for (int c = 0; c < 4; c++) acc[r][c] = 0.f;

#pragma unroll
    for (int ph = 0; ph < 2; ph++) {
        __syncthreads();
        for (int idx = tid; idx < 128 * 128; idx += 256) {
            int j = idx >> 7, k = idx & 127;
            Wt[k * 132 + j] = W2[(size_t)j * H2 + ph * 128 + k];
        }
        __syncthreads();

        const float* Asp = As + ph * 128;
#pragma unroll 2
        for (int k = 0; k < 128; k += 4) {
            float4 w0 = *(const float4*)(Wt + (k + 0) * 132 + tc * 4);
            float4 w1 = *(const float4*)(Wt + (k + 1) * 132 + tc * 4);
            float4 w2 = *(const float4*)(Wt + (k + 2) * 132 + tc * 4);
            float4 w3 = *(const float4*)(Wt + (k + 3) * 132 + tc * 4);
#pragma unroll
            for (int rr = 0; rr < 4; rr++) {
                float4 a = *(const float4*)(Asp + (tr + rr * 8) * 260 + k);
                acc[rr][0] += a.x * w0.x + a.y * w1.x + a.z * w2.x + a.w * w3.x;
                acc[rr][1] += a.x * w0.y + a.y * w1.y + a.z * w2.y + a.w * w3.y;
                acc[rr][2] += a.x * w0.z + a.y * w1.z + a.z * w2.z + a.w * w3.z;
                acc[rr][3] += a.x * w0.w + a.y * w1.w + a.z * w2.w + a.w * w3.w;
            }
        }
    }

    float bb[4];
#pragma unroll
    for (int c = 0; c < 4; c++) bb[c] = b2[tc * 4 + c];

#pragma unroll
    for (int rr = 0; rr < 4; rr++) {
        int gr = row0 + tr + rr * 8;
        if (gr < N) {
            float4 o;
            o.x = acc[rr][0] + bb[0];
            o.y = acc[rr][1] + bb[1];
            o.z = acc[rr][2] + bb[2];
            o.w = acc[rr][3] + bb[3];
            *(float4*)(out + (size_t)gr * HID + tc * 4) = o;
        }
    }
}

// =========================================================================
// launch
// =========================================================================
extern "C" void kernel_launch(void* const* d_in, const int* in_sizes, int n_in,
                              void* d_out, int out_size)
{
    const float* x       = (const float*)d_in[0];
    const int*   ei      = (const int*)  d_in[1];
    const int*   attr    = (const int*)  d_in[2];
    const int*   mask    = (const int*)  d_in[3];
    const float* prelu_a = (const float*)d_in[4];
    const float* Wenc    = (const float*)d_in[5];
    const float* W1      = (const float*)d_in[6];
    const float* b1      = (const float*)d_in[7];
    const float* W2      = (const float*)d_in[8];
    const float* b2      = (const float*)d_in[9];
    const float* emb1    = (const float*)d_in[10];
    const float* emb2    = (const float*)d_in[11];
    float* out = (float*)d_out;

    int N = in_sizes[0] / HID;
    int E = in_sizes[1] / 2;
    int M = in_sizes[3];

    const int SM1 = (128 * 132 + 64 * 132) * 4;   // 101 376 B
    const int SM2 = (128 * 132 + 64 * 132) * 4;   // 101 376 B
    const int SM3 = (128 * 132 + 32 * 260) * 4;   // 100 864 B
    cudaFuncSetAttribute(gemm1_kernel, cudaFuncAttributeMaxDynamicSharedMemorySize, SM1);
    cudaFuncSetAttribute(gemm2_kernel, cudaFuncAttributeMaxDynamicSharedMemorySize, SM2);
    cudaFuncSetAttribute(gemm3_kernel, cudaFuncAttributeMaxDynamicSharedMemorySize, SM3);

    int rowBlocks64 = (N + 63) / 64;
    gemm1_kernel<<<rowBlocks64, 256, SM1>>>(x, Wenc, emb1, emb2, prelu_a, N);      // #1
    if (M > 0) {
        mask_h_kernel<<<M, HID>>>(mask);                                           // #2
        mask_aggr_kernel<<<M, HID>>>(mask, emb1, emb2);                            // #3
    }

    int warps = (E + 31) / 32;
    int eblocks = (warps + 7) / 8;
    if (eblocks < 1) eblocks = 1;
    edge_kernel<<<eblocks, 256>>>(ei, attr, emb1, emb2, E);                        // #4 -> profiled

    dim3 g2(rowBlocks64, 2);
    gemm2_kernel<<<g2, 256, SM2>>>(W1, b1, N);                                     // #5

    int rowBlocks32 = (N + 31) / 32;
    gemm3_kernel<<<rowBlocks32, 256, SM3>>>(W2, b2, out, N);                       // #6
}